// round 1
// baseline (speedup 1.0000x reference)
#include <cuda_runtime.h>
#include <math.h>

#define BB 64
#define SS 4096
#define HH 256
#define TILE 32
#define NCH 8          // S-chunks for output pass

// scratch (device globals: no allocation allowed)
__device__ float g_u[BB * HH];        // W_t @ o_last, per batch
__device__ float g_st[BB * SS];       // scores_time -> alpha_t (in place)
__device__ float g_sf[BB * SS];       // scores_feature -> alpha_f (in place)
__device__ float g_pT[BB * NCH * HH]; // partial weighted sums (time)
__device__ float g_pF[BB * NCH * HH]; // partial weighted sums (feature)

// ---------------------------------------------------------------------------
// Kernel 1: u[b][h] = sum_k W_t[h][k] * o[b, S-1, k]
// ---------------------------------------------------------------------------
__global__ void k_u(const float* __restrict__ o, const float* __restrict__ Wt) {
    int b = blockIdx.x;
    int h = threadIdx.x;
    __shared__ float olast[HH];
    olast[h] = o[((size_t)b * SS + (SS - 1)) * HH + h];
    __syncthreads();
    float acc = 0.f;
    const float* wrow = Wt + h * HH;
#pragma unroll 8
    for (int k = 0; k < HH; k++) acc = fmaf(wrow[k], olast[k], acc);
    g_u[b * HH + h] = acc;
}

// ---------------------------------------------------------------------------
// Kernel 2: per row (b,s):
//   scores_time[b,s]    = dot(o[b,s], u[b])
//   scores_feature[b,s] = sum_k tanh( (o[b,s] @ W_F)[k] ) * v_F[k]
// Block: 256 threads, TILE=32 rows. Thread tid owns feature-column k=tid.
// ---------------------------------------------------------------------------
__global__ void __launch_bounds__(256) k_scores(const float* __restrict__ o,
                                                const float* __restrict__ WF,
                                                const float* __restrict__ vF) {
    int tilei = blockIdx.x;                 // 0 .. B*S/TILE - 1
    int b  = tilei / (SS / TILE);
    int s0 = (tilei % (SS / TILE)) * TILE;
    int tid = threadIdx.x;
    int lane = tid & 31, warp = tid >> 5;

    __shared__ float osh[TILE][HH];         // 32 KB
    __shared__ float ush[HH];
    __shared__ float red[8][TILE];

    ush[tid] = g_u[b * HH + tid];
    const float* obase = o + ((size_t)b * SS + s0) * HH;
#pragma unroll
    for (int r = 0; r < TILE; r++)
        osh[r][tid] = obase[(size_t)r * HH + tid];
    __syncthreads();

    // feature GEMM: z[r] = sum_h o[r][h] * W_F[h][tid]
    float z[TILE];
#pragma unroll
    for (int r = 0; r < TILE; r++) z[r] = 0.f;

    const float* wcol = WF + tid;           // W_F[h*HH + tid]
#pragma unroll 4
    for (int h = 0; h < HH; h++) {
        float w = __ldg(&wcol[h * HH]);
        float4 dummy;
        (void)dummy;
#pragma unroll
        for (int r = 0; r < TILE; r++)
            z[r] = fmaf(osh[r][h], w, z[r]);
    }

    // feature score reduce: sum over k(=tid) of tanh(z)*v[k]
    float v = vF[tid];
#pragma unroll
    for (int r = 0; r < TILE; r++) {
        float t = tanhf(z[r]) * v;
#pragma unroll
        for (int off = 16; off; off >>= 1)
            t += __shfl_xor_sync(0xFFFFFFFFu, t, off);
        if (lane == 0) red[warp][r] = t;
    }
    __syncthreads();
    if (tid < TILE) {
        float sf = 0.f;
#pragma unroll
        for (int w = 0; w < 8; w++) sf += red[w][tid];
        g_sf[b * SS + s0 + tid] = sf;
    }

    // time score: dot(o_row, u) — each warp handles 4 rows
    for (int r = warp; r < TILE; r += 8) {
        float st = 0.f;
#pragma unroll
        for (int h = lane; h < HH; h += 32)
            st = fmaf(osh[r][h], ush[h], st);
#pragma unroll
        for (int off = 16; off; off >>= 1)
            st += __shfl_xor_sync(0xFFFFFFFFu, st, off);
        if (lane == 0) g_st[b * SS + s0 + r] = st;
    }
}

// ---------------------------------------------------------------------------
// Kernel 3: softmax over s (in place). grid = (B, 2): y=0 -> time, y=1 -> feat
// ---------------------------------------------------------------------------
__global__ void k_softmax() {
    int b = blockIdx.x;
    float* p = (blockIdx.y == 0 ? g_st : g_sf) + b * SS;
    __shared__ float vals[SS];              // 16 KB
    __shared__ float red[256];
    int t = threadIdx.x;

    float mx = -1e30f;
    for (int i = t; i < SS; i += 256) {
        float vv = p[i];
        vals[i] = vv;
        mx = fmaxf(mx, vv);
    }
    red[t] = mx; __syncthreads();
    for (int o = 128; o; o >>= 1) {
        if (t < o) red[t] = fmaxf(red[t], red[t + o]);
        __syncthreads();
    }
    mx = red[0]; __syncthreads();

    float sum = 0.f;
    for (int i = t; i < SS; i += 256) {
        float e = expf(vals[i] - mx);
        vals[i] = e;
        sum += e;
    }
    red[t] = sum; __syncthreads();
    for (int o = 128; o; o >>= 1) {
        if (t < o) red[t] += red[t + o];
        __syncthreads();
    }
    float inv = 1.f / red[0];
    for (int i = t; i < SS; i += 256) p[i] = vals[i] * inv;
}

// ---------------------------------------------------------------------------
// Kernel 4: partial weighted sums over an S-chunk. grid = (NCH, B), 256 thr.
// ---------------------------------------------------------------------------
__global__ void __launch_bounds__(256) k_out(const float* __restrict__ o) {
    int ch = blockIdx.x, b = blockIdx.y, h = threadIdx.x;
    int s0 = ch * (SS / NCH);
    const float* ob = o + ((size_t)b * SS + s0) * HH;
    const float* at = g_st + b * SS + s0;
    const float* af = g_sf + b * SS + s0;
    float aT = 0.f, aF = 0.f;
#pragma unroll 4
    for (int s = 0; s < SS / NCH; s++) {
        float ov = ob[(size_t)s * HH + h];
        float wt = __ldg(&at[s]);
        float wf = __ldg(&af[s]);
        aT = fmaf(wt, ov, aT);
        aF = fmaf(wf, ov, aF);
    }
    g_pT[(b * NCH + ch) * HH + h] = aT;
    g_pF[(b * NCH + ch) * HH + h] = aF;
}

// ---------------------------------------------------------------------------
// Kernel 5: reduce partials -> out (B, 2H) row-major, [T | F]
// ---------------------------------------------------------------------------
__global__ void k_reduce(float* __restrict__ out) {
    int b = blockIdx.x;
    int t = threadIdx.x;                    // 512
    float a = 0.f;
    if (t < HH) {
#pragma unroll
        for (int c = 0; c < NCH; c++) a += g_pT[(b * NCH + c) * HH + t];
        out[b * 2 * HH + t] = a;
    } else {
        int h = t - HH;
#pragma unroll
        for (int c = 0; c < NCH; c++) a += g_pF[(b * NCH + c) * HH + h];
        out[b * 2 * HH + HH + h] = a;
    }
}

// ---------------------------------------------------------------------------
extern "C" void kernel_launch(void* const* d_in, const int* in_sizes, int n_in,
                              void* d_out, int out_size) {
    const float* o  = (const float*)d_in[0];   // (B, S, H)
    const float* Wt = (const float*)d_in[1];   // (H, H)
    const float* WF = (const float*)d_in[2];   // (H, H)
    const float* vF = (const float*)d_in[3];   // (H, 1)
    float* out = (float*)d_out;                // (B, 2H)

    k_u<<<BB, HH>>>(o, Wt);
    k_scores<<<BB * SS / TILE, 256>>>(o, WF, vF);
    k_softmax<<<dim3(BB, 2), 256>>>();
    k_out<<<dim3(NCH, BB), HH>>>(o);
    k_reduce<<<BB, 2 * HH>>>(out);
}

// round 3
// speedup vs baseline: 6.3800x; 6.3800x over previous
#include <cuda_runtime.h>
#include <math.h>
#include <stdint.h>

#define BB 64
#define SS 4096
#define HH 256
#define TM 128
#define NTILES 2048            // BB*SS/TM

// ---------------- device-global scratch (no allocation allowed) -------------
__device__ float g_u[BB * HH];              // W_t @ o_last per batch
__device__ float g_Bfrag[32 * 16 * 32 * 4]; // W_F^T, tf32-rounded, mma-fragment order (256 KB)
__device__ float g_pT[NTILES * HH];
__device__ float g_pF[NTILES * HH];
__device__ float g_mT[NTILES], g_sT[NTILES], g_mF[NTILES], g_sF[NTILES];

// ---------------- SMEM map (bytes) ------------------------------------------
#define A_OFF     0            // 8 chunks x (128 rows x 128B) = 131072
#define B_OFF     131072       // 2 slots x 32768 = 65536
#define VSH_OFF   196608       // 256 floats
#define SCT_OFF   197632       // 128 floats
#define SCF_OFF   198144       // 128 floats
#define SCFR_OFF  198656       // 4 x 128 floats = 2048
#define RED_OFF   200704       // 32 floats
#define SMEM_TOTAL 200832

// ---------------- small helpers ---------------------------------------------
__device__ __forceinline__ uint32_t tf32u(float x) {
    uint32_t u;
    asm("cvt.rna.tf32.f32 %0, %1;" : "=r"(u) : "f"(x));
    return u;
}
__device__ __forceinline__ float tf32f(float x) { return __uint_as_float(tf32u(x)); }
__device__ __forceinline__ float tanha(float x) {
    float y;
    asm("tanh.approx.f32 %0, %1;" : "=f"(y) : "f"(x));
    return y;
}
__device__ __forceinline__ void mma8(float* c, uint32_t a0, uint32_t a1,
                                     uint32_t a2, uint32_t a3,
                                     uint32_t b0, uint32_t b1) {
    asm volatile(
        "mma.sync.aligned.m16n8k8.row.col.f32.tf32.tf32.f32 "
        "{%0,%1,%2,%3}, {%4,%5,%6,%7}, {%8,%9}, {%0,%1,%2,%3};"
        : "+f"(c[0]), "+f"(c[1]), "+f"(c[2]), "+f"(c[3])
        : "r"(a0), "r"(a1), "r"(a2), "r"(a3), "r"(b0), "r"(b1));
}

// ---------------------------------------------------------------------------
// k_u: u[b][h] = sum_k W_t[h][k] * o[b, S-1, k]   (exact fp32)
// ---------------------------------------------------------------------------
__global__ void k_u(const float* __restrict__ o, const float* __restrict__ Wt) {
    int b = blockIdx.x, h = threadIdx.x;
    __shared__ float olast[HH];
    olast[h] = o[((size_t)b * SS + (SS - 1)) * HH + h];
    __syncthreads();
    float acc = 0.f;
    const float* wrow = Wt + h * HH;
#pragma unroll 8
    for (int k = 0; k < HH; k++) acc = fmaf(wrow[k], olast[k], acc);
    g_u[b * HH + h] = acc;
}

// ---------------------------------------------------------------------------
// k_prep: build W_F^T in tf32, laid out in exact m16n8k8 B-fragment order.
// Index: [kstep t (32)][ntile-pair p (16)][lane (32)] -> float4
//   .x = B[k0+(l&3)][na]   .y = B[k0+4+(l&3)][na]   (ntile 2p)
//   .z = B[k0+(l&3)][nb]   .w = B[k0+4+(l&3)][nb]   (ntile 2p+1)
// where k0 = 8t, na = 16p + (l>>2), nb = na+8, B[k][n] = W_F[k*HH + n].
// ---------------------------------------------------------------------------
__global__ void k_prep(const float* __restrict__ WF) {
    int t = blockIdx.x;  // 0..31
#pragma unroll
    for (int it = 0; it < 2; it++) {
        int idx = threadIdx.x + it * 256;  // 0..511
        int p = idx >> 5, l = idx & 31;
        int k = t * 8 + (l & 3);
        int na = p * 16 + (l >> 2);
        int nb = na + 8;
        float4 q;
        q.x = tf32f(WF[k * HH + na]);
        q.y = tf32f(WF[(k + 4) * HH + na]);
        q.z = tf32f(WF[k * HH + nb]);
        q.w = tf32f(WF[(k + 4) * HH + nb]);
        ((float4*)g_Bfrag)[(t * 16 + p) * 32 + l] = q;
    }
}

// ---------------------------------------------------------------------------
// k_main: fused feature GEMM (mma.sync tf32) + tanh·v_F scores + time scores +
//         split-softmax partials + partial weighted sums. grid=2048, block=256.
// ---------------------------------------------------------------------------
__global__ void __launch_bounds__(256, 1)
k_main(const float* __restrict__ o, const float* __restrict__ vF) {
    extern __shared__ __align__(16) char smem[];
    const int tid = threadIdx.x, lane = tid & 31, wid = tid >> 5;
    const int tile = blockIdx.x;
    const int b = tile >> 5, s0 = (tile & 31) << 7;
    const int mw = wid & 1;   // M half (64 rows)
    const int nw = wid >> 1;  // N quarter (64 cols = 8 ntiles)
    const int rq = lane >> 2, cq = lane & 3;
    const uint32_t xr = (uint32_t)rq << 4;

    float* vsh   = (float*)(smem + VSH_OFF);
    float* scT   = (float*)(smem + SCT_OFF);
    float* scF   = (float*)(smem + SCF_OFF);
    float* scFr  = (float*)(smem + SCFR_OFF);
    float* red   = (float*)(smem + RED_OFF);

    const float* obase = o + ((size_t)(b * SS + s0)) * HH;

    // ---- B chunk 0 prefetch (regs) ----
    float4 pre[8];
    {
        const float4* src = (const float4*)g_Bfrag + tid;
#pragma unroll
        for (int i = 0; i < 8; i++) pre[i] = __ldg(src + i * 256);
    }

    // ---- load A tile (128x256 fp32) into swizzled K-chunked SMEM ----
    // chunk kc holds cols [32kc, 32kc+32), 128B rows, XOR swizzle per row.
#pragma unroll 1
    for (int rep = 0; rep < 4; rep++) {
        float4 v[8];
#pragma unroll
        for (int i = 0; i < 8; i++) {
            int f4 = (rep * 8 + i) * 256 + tid;      // 0..8191
            int row = f4 >> 6, g = f4 & 63;
            v[i] = __ldg((const float4*)obase + (size_t)row * 64 + g);
        }
#pragma unroll
        for (int i = 0; i < 8; i++) {
            int f4 = (rep * 8 + i) * 256 + tid;
            int row = f4 >> 6, g = f4 & 63;
            int kc = g >> 3, c8 = g & 7;
            uint32_t off = (uint32_t)kc * 16384 + (uint32_t)row * 128 +
                           (((uint32_t)c8 * 16) ^ (((uint32_t)(row & 7)) << 4));
            *(float4*)(smem + A_OFF + off) = v[i];
        }
    }
    vsh[tid] = __ldg(&vF[tid]);
    // store B chunk 0 into slot 0 (linear fragment order)
    {
        float4* dst = (float4*)(smem + B_OFF) + tid;
#pragma unroll
        for (int i = 0; i < 8; i++) dst[i * 256] = pre[i];
    }
    __syncthreads();

    // ---- per-warp A row base offsets (bytes within a chunk) ----
    uint32_t rowoff[4];
#pragma unroll
    for (int mi = 0; mi < 4; mi++)
        rowoff[mi] = (uint32_t)(mw * 64 + mi * 16 + rq) * 128;

    float acc[4][8][4];
#pragma unroll
    for (int mi = 0; mi < 4; mi++)
#pragma unroll
        for (int ni = 0; ni < 8; ni++)
#pragma unroll
            for (int j = 0; j < 4; j++) acc[mi][ni][j] = 0.f;

    // ---- mainloop over 8 K-chunks of 32 ----
#pragma unroll 1
    for (int kc = 0; kc < 8; kc++) {
        float4 nxt[8];
        if (kc < 7) {
            const float4* src = (const float4*)g_Bfrag + (kc + 1) * 2048 + tid;
#pragma unroll
            for (int i = 0; i < 8; i++) nxt[i] = __ldg(src + i * 256);
        }
        const char* Ach = smem + A_OFF + kc * 16384;
        const float4* Bsl = (const float4*)(smem + B_OFF + (kc & 1) * 32768);
#pragma unroll
        for (int ti = 0; ti < 4; ti++) {
            uint32_t ko = (uint32_t)(ti * 32 + cq * 4);
            uint32_t o1 = ko ^ xr;
            uint32_t o2 = (ko + 16) ^ xr;
            uint32_t a[4][4];
#pragma unroll
            for (int mi = 0; mi < 4; mi++) {
                const char* pb = Ach + rowoff[mi];
                a[mi][0] = tf32u(*(const float*)(pb + o1));
                a[mi][1] = tf32u(*(const float*)(pb + 1024 + o1));
                a[mi][2] = tf32u(*(const float*)(pb + o2));
                a[mi][3] = tf32u(*(const float*)(pb + 1024 + o2));
            }
            const float4* bp = Bsl + (ti * 16 + nw * 4) * 32 + lane;
#pragma unroll
            for (int p = 0; p < 4; p++) {
                float4 bq = bp[p * 32];
                uint32_t b0 = __float_as_uint(bq.x), b1 = __float_as_uint(bq.y);
                uint32_t b2 = __float_as_uint(bq.z), b3 = __float_as_uint(bq.w);
#pragma unroll
                for (int mi = 0; mi < 4; mi++) {
                    mma8(acc[mi][2 * p],     a[mi][0], a[mi][1], a[mi][2], a[mi][3], b0, b1);
                    mma8(acc[mi][2 * p + 1], a[mi][0], a[mi][1], a[mi][2], a[mi][3], b2, b3);
                }
            }
        }
        if (kc < 7) {
            float4* dst = (float4*)(smem + B_OFF + ((kc + 1) & 1) * 32768) + tid;
#pragma unroll
            for (int i = 0; i < 8; i++) dst[i * 256] = nxt[i];
            __syncthreads();
        }
    }

    // ---- feature scores: sf[r] = sum_n tanh(z[r,n]) * v[n] ----
#pragma unroll
    for (int mi = 0; mi < 4; mi++) {
        float s0 = 0.f, s1 = 0.f;
#pragma unroll
        for (int ni = 0; ni < 8; ni++) {
            int n = nw * 64 + ni * 8 + cq * 2;
            float v0 = vsh[n], v1 = vsh[n + 1];
            s0 = fmaf(tanha(acc[mi][ni][0]), v0, s0);
            s0 = fmaf(tanha(acc[mi][ni][1]), v1, s0);
            s1 = fmaf(tanha(acc[mi][ni][2]), v0, s1);
            s1 = fmaf(tanha(acc[mi][ni][3]), v1, s1);
        }
        s0 += __shfl_xor_sync(0xFFFFFFFFu, s0, 1);
        s0 += __shfl_xor_sync(0xFFFFFFFFu, s0, 2);
        s1 += __shfl_xor_sync(0xFFFFFFFFu, s1, 1);
        s1 += __shfl_xor_sync(0xFFFFFFFFu, s1, 2);
        if (cq == 0) {
            int r = mw * 64 + mi * 16 + rq;
            scFr[nw * 128 + r] = s0;
            scFr[nw * 128 + r + 8] = s1;
        }
    }

    // ---- time scores (exact fp32 from SMEM A): warp wid owns rows 16w..16w+15
    {
        float uv[8];
#pragma unroll
        for (int kc = 0; kc < 8; kc++) uv[kc] = __ldg(&g_u[b * HH + kc * 32 + lane]);
#pragma unroll 1
        for (int rr = 0; rr < 16; rr++) {
            int r = wid * 16 + rr;
            uint32_t co = ((uint32_t)lane * 4) ^ (((uint32_t)(r & 7)) << 4);
            float a2 = 0.f;
#pragma unroll
            for (int kc = 0; kc < 8; kc++) {
                float av = *(const float*)(smem + A_OFF + kc * 16384 + r * 128 + co);
                a2 = fmaf(av, uv[kc], a2);
            }
#pragma unroll
            for (int off = 16; off; off >>= 1)
                a2 += __shfl_xor_sync(0xFFFFFFFFu, a2, off);
            if (lane == 0) scT[r] = a2;
        }
    }
    __syncthreads();
    if (tid < 128)
        scF[tid] = scFr[tid] + scFr[128 + tid] + scFr[256 + tid] + scFr[384 + tid];
    __syncthreads();

    // ---- split-softmax partials for both arrays ----
    float* arr = (tid < 128) ? scT : scF;
    int i = tid & 127;
    float v = arr[i];
    float m = v;
#pragma unroll
    for (int off = 16; off; off >>= 1)
        m = fmaxf(m, __shfl_xor_sync(0xFFFFFFFFu, m, off));
    if (lane == 0) red[wid] = m;
    __syncthreads();
    float M = (tid < 128)
        ? fmaxf(fmaxf(red[0], red[1]), fmaxf(red[2], red[3]))
        : fmaxf(fmaxf(red[4], red[5]), fmaxf(red[6], red[7]));
    float e = __expf(v - M);
    float s = e;
#pragma unroll
    for (int off = 16; off; off >>= 1)
        s += __shfl_xor_sync(0xFFFFFFFFu, s, off);
    __syncthreads();
    arr[i] = e;
    if (lane == 0) red[wid] = s;
    __syncthreads();
    if (tid == 0)   { g_mT[tile] = M; g_sT[tile] = red[0] + red[1] + red[2] + red[3]; }
    if (tid == 128) { g_mF[tile] = M; g_sF[tile] = red[4] + red[5] + red[6] + red[7]; }

    // ---- partial weighted sums: thread owns h = tid ----
    float aT = 0.f, aF = 0.f;
    const char* abase = smem + A_OFF + (tid >> 5) * 16384;
    uint32_t coff = (uint32_t)(tid & 31) * 4;
#pragma unroll 4
    for (int r = 0; r < TM; r++) {
        float wT = scT[r], wF = scF[r];
        float ov = *(const float*)(abase + r * 128 + (coff ^ (((uint32_t)(r & 7)) << 4)));
        aT = fmaf(wT, ov, aT);
        aF = fmaf(wF, ov, aF);
    }
    g_pT[tile * HH + tid] = aT;
    g_pF[tile * HH + tid] = aF;
}

// ---------------------------------------------------------------------------
// k_combine: exact split-softmax merge across the 32 s-tiles of each batch
// ---------------------------------------------------------------------------
__global__ void k_combine(float* __restrict__ out) {
    int b = blockIdx.x, h = threadIdx.x;
    float MT = -1e30f, MF = -1e30f;
#pragma unroll
    for (int c = 0; c < 32; c++) {
        MT = fmaxf(MT, g_mT[b * 32 + c]);
        MF = fmaxf(MF, g_mF[b * 32 + c]);
    }
    float ST = 0.f, SF = 0.f, oT = 0.f, oF = 0.f;
#pragma unroll
    for (int c = 0; c < 32; c++) {
        int t = b * 32 + c;
        float wT = __expf(g_mT[t] - MT), wF = __expf(g_mF[t] - MF);
        ST = fmaf(wT, g_sT[t], ST);
        SF = fmaf(wF, g_sF[t], SF);
        oT = fmaf(wT, g_pT[t * HH + h], oT);
        oF = fmaf(wF, g_pF[t * HH + h], oF);
    }
    out[b * 2 * HH + h] = oT / ST;
    out[b * 2 * HH + HH + h] = oF / SF;
}

// ---------------------------------------------------------------------------
extern "C" void kernel_launch(void* const* d_in, const int* in_sizes, int n_in,
                              void* d_out, int out_size) {
    const float* o  = (const float*)d_in[0];
    const float* Wt = (const float*)d_in[1];
    const float* WF = (const float*)d_in[2];
    const float* vF = (const float*)d_in[3];
    float* out = (float*)d_out;

    cudaFuncSetAttribute(k_main, cudaFuncAttributeMaxDynamicSharedMemorySize, SMEM_TOTAL);

    k_u<<<BB, HH>>>(o, Wt);
    k_prep<<<32, 256>>>(WF);
    k_main<<<NTILES, 256, SMEM_TOTAL>>>(o, vF);
    k_combine<<<BB, HH>>>(out);
}

// round 4
// speedup vs baseline: 8.3081x; 1.3022x over previous
#include <cuda_runtime.h>
#include <cuda_fp16.h>
#include <math.h>
#include <stdint.h>

#define BB 64
#define SS 4096
#define HH 256
#define TM 128
#define NTILES 2048            // BB*SS/TM

// ---------------- device-global scratch (no allocation allowed) -------------
__device__ float g_u[BB * HH];            // W_t @ o_last per batch
__device__ uint4 g_Bh[16 * 16 * 32];      // W_F in fp16 m16n8k16 B-fragment order (128 KB)
__device__ float g_pT[NTILES * HH];
__device__ float g_pF[NTILES * HH];
__device__ float g_mT[NTILES], g_sT[NTILES], g_mF[NTILES], g_sF[NTILES];

// ---------------- SMEM map (bytes) ------------------------------------------
#define A_OFF     0            // 8 chunks x (128 rows x 128B) = 131072 (fp32, swizzled)
#define B_OFF     131072       // 3 slots x 16384 = 49152 (fp16 fragments)
#define VSH_OFF   180224       // 256 floats
#define SCT_OFF   181248       // 128 floats
#define SCF_OFF   181760       // 128 floats
#define SCFR_OFF  182272       // 4 x 128 floats
#define RED_OFF   184320       // 32 floats
#define SMEM_TOTAL 184448

// ---------------- helpers ----------------------------------------------------
__device__ __forceinline__ uint32_t packh2(float lo, float hi) {
    __half2 h = __floats2half2_rn(lo, hi);
    return *(uint32_t*)&h;
}
__device__ __forceinline__ float tanha(float x) {
    float y;
    asm("tanh.approx.f32 %0, %1;" : "=f"(y) : "f"(x));
    return y;
}
__device__ __forceinline__ void mma16(float* c, uint32_t a0, uint32_t a1,
                                      uint32_t a2, uint32_t a3,
                                      uint32_t b0, uint32_t b1) {
    asm volatile(
        "mma.sync.aligned.m16n8k16.row.col.f32.f16.f16.f32 "
        "{%0,%1,%2,%3}, {%4,%5,%6,%7}, {%8,%9}, {%0,%1,%2,%3};"
        : "+f"(c[0]), "+f"(c[1]), "+f"(c[2]), "+f"(c[3])
        : "r"(a0), "r"(a1), "r"(a2), "r"(a3), "r"(b0), "r"(b1));
}
#define CP16(dst, src) \
    asm volatile("cp.async.cg.shared.global [%0], [%1], 16;" :: "r"(dst), "l"(src) : "memory")
#define CPCOMMIT() asm volatile("cp.async.commit_group;" ::: "memory")
template<int N> __device__ __forceinline__ void cpwait() {
    asm volatile("cp.async.wait_group %0;" :: "n"(N) : "memory");
}
__device__ __forceinline__ uint32_t s2u(const void* p) {
    uint32_t a;
    asm("{ .reg .u64 t; cvta.to.shared.u64 t, %1; cvt.u32.u64 %0, t; }" : "=r"(a) : "l"(p));
    return a;
}

// ---------------------------------------------------------------------------
// k_u: u[b][h] = sum_k W_t[h][k] * o[b, S-1, k]   (exact fp32)
// ---------------------------------------------------------------------------
__global__ void k_u(const float* __restrict__ o, const float* __restrict__ Wt) {
    int b = blockIdx.x, h = threadIdx.x;
    __shared__ float olast[HH];
    olast[h] = o[((size_t)b * SS + (SS - 1)) * HH + h];
    __syncthreads();
    float acc = 0.f;
    const float* wrow = Wt + h * HH;
#pragma unroll 8
    for (int k = 0; k < HH; k++) acc = fmaf(wrow[k], olast[k], acc);
    g_u[b * HH + h] = acc;
}

// ---------------------------------------------------------------------------
// k_prep: W_F -> fp16 m16n8k16 B-fragment image.
// Fragment B[k][n] (k inner within 16-step t): for lane (rq=l>>2, cq=l&3),
// pair p covers n-tiles 2p, 2p+1:
//   q.x = {B[k0+2cq][na], B[k0+2cq+1][na]}   q.y = {B[k0+2cq+8][na], B[k0+2cq+9][na]}
//   q.z/.w = same for nb = na+8;  na = 16p + rq;  B[k][n] = W_F[k*HH + n]
// ---------------------------------------------------------------------------
__global__ void k_prep(const float* __restrict__ WF) {
    int t = blockIdx.x;                 // kstep 0..15
    int tid = threadIdx.x;              // 512
    int p = tid >> 5, l = tid & 31;
    int rq = l >> 2, cq = l & 3;
    int k0 = t * 16 + 2 * cq;
    int na = p * 16 + rq, nb = na + 8;
    uint4 q;
    q.x = packh2(WF[k0 * HH + na],       WF[(k0 + 1) * HH + na]);
    q.y = packh2(WF[(k0 + 8) * HH + na], WF[(k0 + 9) * HH + na]);
    q.z = packh2(WF[k0 * HH + nb],       WF[(k0 + 1) * HH + nb]);
    q.w = packh2(WF[(k0 + 8) * HH + nb], WF[(k0 + 9) * HH + nb]);
    g_Bh[(t * 16 + p) * 32 + l] = q;
}

// ---------------------------------------------------------------------------
// k_main: fused feature GEMM (fp16 mma) + tanh·v_F + exact time scores +
//         split-softmax partials + partial weighted sums. grid=2048, block=256.
// ---------------------------------------------------------------------------
__global__ void __launch_bounds__(256, 1)
k_main(const float* __restrict__ o, const float* __restrict__ vF) {
    extern __shared__ __align__(16) char smem[];
    const uint32_t sb = s2u(smem);
    const int tid = threadIdx.x, lane = tid & 31, wid = tid >> 5;
    const int tile = blockIdx.x;
    const int b = tile >> 5, s0 = (tile & 31) << 7;
    const int mw = wid & 1;   // M half (64 rows)
    const int nw = wid >> 1;  // N quarter (64 cols)
    const int rq = lane >> 2, cq = lane & 3;
    const uint32_t xr = (uint32_t)rq << 4;

    float* vsh  = (float*)(smem + VSH_OFF);
    float* scT  = (float*)(smem + SCT_OFF);
    float* scF  = (float*)(smem + SCF_OFF);
    float* scFr = (float*)(smem + SCFR_OFF);
    float* red  = (float*)(smem + RED_OFF);

    const float* obase = o + ((size_t)(b * SS + s0)) * HH;

    // chunk issue: A chunk c (16 KB fp32 swizzled) + B chunk c (16 KB fragments)
    auto issue = [&](int c) {
#pragma unroll
        for (int j = 0; j < 4; j++) {
            int f4 = tid + j * 256;              // 0..1023
            int row = f4 >> 3, c8 = f4 & 7;
            const float* src = obase + (size_t)row * HH + c * 32 + c8 * 4;
            uint32_t dst = sb + A_OFF + c * 16384 + row * 128 +
                           (((uint32_t)c8 * 16) ^ (((uint32_t)(row & 7)) << 4));
            CP16(dst, src);
        }
        uint32_t bdst = sb + B_OFF + (c % 3) * 16384;
        const uint4* bsrc = g_Bh + c * 1024;
#pragma unroll
        for (int j = 0; j < 4; j++) {
            int idx = tid + j * 256;
            CP16(bdst + idx * 16, (const void*)(bsrc + idx));
        }
        CPCOMMIT();
    };

    vsh[tid] = __ldg(&vF[tid]);
    issue(0);
    issue(1);

    uint32_t rowoff[4];
#pragma unroll
    for (int mi = 0; mi < 4; mi++)
        rowoff[mi] = (uint32_t)(mw * 64 + mi * 16 + rq) * 128;

    float acc[4][8][4];
#pragma unroll
    for (int mi = 0; mi < 4; mi++)
#pragma unroll
        for (int ni = 0; ni < 8; ni++)
#pragma unroll
            for (int j = 0; j < 4; j++) acc[mi][ni][j] = 0.f;

    // ---- pipelined mainloop over 8 K-chunks of 32 ----
#pragma unroll 1
    for (int c = 0; c < 8; c++) {
        if (c < 7) cpwait<1>(); else cpwait<0>();
        __syncthreads();
        if (c <= 5) issue(c + 2);

        const char* Ach = smem + A_OFF + c * 16384;
        const uint4* Bsl = (const uint4*)(smem + B_OFF + (c % 3) * 16384);
#pragma unroll
        for (int t = 0; t < 2; t++) {
            uint32_t a[4][4];
            uint32_t o1 = ((uint32_t)(t * 64 + cq * 8)) ^ xr;
            uint32_t o2 = ((uint32_t)(t * 64 + cq * 8 + 32)) ^ xr;
#pragma unroll
            for (int mi = 0; mi < 4; mi++) {
                const char* pb = Ach + rowoff[mi];
                float2 f0 = *(const float2*)(pb + o1);
                float2 f1 = *(const float2*)(pb + 1024 + o1);
                float2 f2 = *(const float2*)(pb + o2);
                float2 f3 = *(const float2*)(pb + 1024 + o2);
                a[mi][0] = packh2(f0.x, f0.y);
                a[mi][1] = packh2(f1.x, f1.y);
                a[mi][2] = packh2(f2.x, f2.y);
                a[mi][3] = packh2(f3.x, f3.y);
            }
            const uint4* bp = Bsl + (t * 16 + nw * 4) * 32 + lane;
#pragma unroll
            for (int p = 0; p < 4; p++) {
                uint4 bq = bp[p * 32];
#pragma unroll
                for (int mi = 0; mi < 4; mi++) {
                    mma16(acc[mi][2 * p],     a[mi][0], a[mi][1], a[mi][2], a[mi][3], bq.x, bq.y);
                    mma16(acc[mi][2 * p + 1], a[mi][0], a[mi][1], a[mi][2], a[mi][3], bq.z, bq.w);
                }
            }
        }
    }

    // ---- feature scores: sf[r] = sum_n tanh(z[r,n]) * v[n] ----
#pragma unroll
    for (int mi = 0; mi < 4; mi++) {
        float s0a = 0.f, s1a = 0.f;
#pragma unroll
        for (int ni = 0; ni < 8; ni++) {
            int n = nw * 64 + ni * 8 + cq * 2;
            float v0 = vsh[n], v1 = vsh[n + 1];
            s0a = fmaf(tanha(acc[mi][ni][0]), v0, s0a);
            s0a = fmaf(tanha(acc[mi][ni][1]), v1, s0a);
            s1a = fmaf(tanha(acc[mi][ni][2]), v0, s1a);
            s1a = fmaf(tanha(acc[mi][ni][3]), v1, s1a);
        }
        s0a += __shfl_xor_sync(0xFFFFFFFFu, s0a, 1);
        s0a += __shfl_xor_sync(0xFFFFFFFFu, s0a, 2);
        s1a += __shfl_xor_sync(0xFFFFFFFFu, s1a, 1);
        s1a += __shfl_xor_sync(0xFFFFFFFFu, s1a, 2);
        if (cq == 0) {
            int r = mw * 64 + mi * 16 + rq;
            scFr[nw * 128 + r] = s0a;
            scFr[nw * 128 + r + 8] = s1a;
        }
    }

    // ---- exact fp32 time scores from SMEM A: warp wid owns rows 16w..16w+15
    {
        float uv[8];
#pragma unroll
        for (int kc = 0; kc < 8; kc++) uv[kc] = __ldg(&g_u[b * HH + kc * 32 + lane]);
#pragma unroll 1
        for (int rr = 0; rr < 16; rr++) {
            int r = wid * 16 + rr;
            uint32_t co = ((uint32_t)lane * 4) ^ (((uint32_t)(r & 7)) << 4);
            float a2 = 0.f;
#pragma unroll
            for (int kc = 0; kc < 8; kc++) {
                float av = *(const float*)(smem + A_OFF + kc * 16384 + r * 128 + co);
                a2 = fmaf(av, uv[kc], a2);
            }
#pragma unroll
            for (int off = 16; off; off >>= 1)
                a2 += __shfl_xor_sync(0xFFFFFFFFu, a2, off);
            if (lane == 0) scT[r] = a2;
        }
    }
    __syncthreads();
    if (tid < 128)
        scF[tid] = scFr[tid] + scFr[128 + tid] + scFr[256 + tid] + scFr[384 + tid];
    __syncthreads();

    // ---- split-softmax partials for both arrays ----
    float* arr = (tid < 128) ? scT : scF;
    int i = tid & 127;
    float v = arr[i];
    float m = v;
#pragma unroll
    for (int off = 16; off; off >>= 1)
        m = fmaxf(m, __shfl_xor_sync(0xFFFFFFFFu, m, off));
    if (lane == 0) red[wid] = m;
    __syncthreads();
    float M = (tid < 128)
        ? fmaxf(fmaxf(red[0], red[1]), fmaxf(red[2], red[3]))
        : fmaxf(fmaxf(red[4], red[5]), fmaxf(red[6], red[7]));
    float e = __expf(v - M);
    float s = e;
#pragma unroll
    for (int off = 16; off; off >>= 1)
        s += __shfl_xor_sync(0xFFFFFFFFu, s, off);
    __syncthreads();
    arr[i] = e;
    if (lane == 0) red[wid] = s;
    __syncthreads();
    if (tid == 0)   { g_mT[tile] = M; g_sT[tile] = red[0] + red[1] + red[2] + red[3]; }
    if (tid == 128) { g_mF[tile] = M; g_sF[tile] = red[4] + red[5] + red[6] + red[7]; }

    // ---- partial weighted sums: thread owns h = tid ----
    float aT = 0.f, aF = 0.f;
    const char* abase = smem + A_OFF + (tid >> 5) * 16384;
    uint32_t coff = (uint32_t)(tid & 31) * 4;
#pragma unroll 4
    for (int r = 0; r < TM; r++) {
        float wT = scT[r], wF = scF[r];
        float ov = *(const float*)(abase + r * 128 + (coff ^ (((uint32_t)(r & 7)) << 4)));
        aT = fmaf(wT, ov, aT);
        aF = fmaf(wF, ov, aF);
    }
    g_pT[tile * HH + tid] = aT;
    g_pF[tile * HH + tid] = aF;
}

// ---------------------------------------------------------------------------
// k_combine: exact split-softmax merge across the 32 s-tiles of each batch
// ---------------------------------------------------------------------------
__global__ void k_combine(float* __restrict__ out) {
    int b = blockIdx.x, h = threadIdx.x;
    float MT = -1e30f, MF = -1e30f;
#pragma unroll
    for (int c = 0; c < 32; c++) {
        MT = fmaxf(MT, g_mT[b * 32 + c]);
        MF = fmaxf(MF, g_mF[b * 32 + c]);
    }
    float ST = 0.f, SF = 0.f, oT = 0.f, oF = 0.f;
#pragma unroll
    for (int c = 0; c < 32; c++) {
        int t = b * 32 + c;
        float wT = __expf(g_mT[t] - MT), wF = __expf(g_mF[t] - MF);
        ST = fmaf(wT, g_sT[t], ST);
        SF = fmaf(wF, g_sF[t], SF);
        oT = fmaf(wT, g_pT[t * HH + h], oT);
        oF = fmaf(wF, g_pF[t * HH + h], oF);
    }
    out[b * 2 * HH + h] = oT / ST;
    out[b * 2 * HH + HH + h] = oF / SF;
}

// ---------------------------------------------------------------------------
extern "C" void kernel_launch(void* const* d_in, const int* in_sizes, int n_in,
                              void* d_out, int out_size) {
    const float* o  = (const float*)d_in[0];
    const float* Wt = (const float*)d_in[1];
    const float* WF = (const float*)d_in[2];
    const float* vF = (const float*)d_in[3];
    float* out = (float*)d_out;

    cudaFuncSetAttribute(k_main, cudaFuncAttributeMaxDynamicSharedMemorySize, SMEM_TOTAL);

    k_u<<<BB, HH>>>(o, Wt);
    k_prep<<<16, 512>>>(WF);
    k_main<<<NTILES, 256, SMEM_TOTAL>>>(o, vF);
    k_combine<<<BB, HH>>>(out);
}

// round 5
// speedup vs baseline: 9.7378x; 1.1721x over previous
#include <cuda_runtime.h>
#include <cuda_fp16.h>
#include <math.h>
#include <stdint.h>

#define BB 64
#define SS 4096
#define HH 256
#define TM 128
#define NTILES 2048            // BB*SS/TM

// ---------------- device-global scratch (no allocation allowed) -------------
__device__ float g_u[BB * HH];            // W_t @ o_last per batch (fp32)
__device__ uint4 g_Bh[16 * 16 * 32];      // W_F fp16 m16n8k16 B-fragment image (128 KB)
__device__ float g_pT[NTILES * HH];
__device__ float g_pF[NTILES * HH];
__device__ float g_mT[NTILES], g_sT[NTILES], g_mF[NTILES], g_sF[NTILES];

// ---------------- SMEM map (bytes) ------------------------------------------
#define AH_OFF    0            // 8 chunks x (128 rows x 64B fp16) = 65536
#define B_OFF     65536        // 3 slots x 16384 = 49152 (fp16 fragments)
#define UH_OFF    114688       // 128 uint32 (u as half2) = 512
#define VSH_OFF   115200       // 256 floats
#define SCT_OFF   116224       // 128 floats
#define SCF_OFF   116736       // 128 floats
#define SCTP_OFF  117248       // 4 x 128 floats
#define SCFR_OFF  119296       // 4 x 128 floats
#define RED_OFF   121344       // 32 floats
#define SMEM_TOTAL 121472
// weighted-sum partials reuse the B region after the mainloop:
#define PTS_OFF   B_OFF                 // 4 x 256 floats
#define PFS_OFF   (B_OFF + 4096)        // 4 x 256 floats

// ---------------- helpers ----------------------------------------------------
__device__ __forceinline__ uint32_t packh2(float lo, float hi) {
    __half2 h = __floats2half2_rn(lo, hi);
    return *(uint32_t*)&h;
}
__device__ __forceinline__ float tanha(float x) {
    float y;
    asm("tanh.approx.f32 %0, %1;" : "=f"(y) : "f"(x));
    return y;
}
__device__ __forceinline__ void mma16(float* c, uint32_t a0, uint32_t a1,
                                      uint32_t a2, uint32_t a3,
                                      uint32_t b0, uint32_t b1) {
    asm volatile(
        "mma.sync.aligned.m16n8k16.row.col.f32.f16.f16.f32 "
        "{%0,%1,%2,%3}, {%4,%5,%6,%7}, {%8,%9}, {%0,%1,%2,%3};"
        : "+f"(c[0]), "+f"(c[1]), "+f"(c[2]), "+f"(c[3])
        : "r"(a0), "r"(a1), "r"(a2), "r"(a3), "r"(b0), "r"(b1));
}
__device__ __forceinline__ void ldsm4(uint32_t* a, uint32_t addr) {
    asm volatile("ldmatrix.sync.aligned.m8n8.x4.shared.b16 {%0,%1,%2,%3}, [%4];"
                 : "=r"(a[0]), "=r"(a[1]), "=r"(a[2]), "=r"(a[3]) : "r"(addr));
}
#define CP16(dst, src) \
    asm volatile("cp.async.cg.shared.global [%0], [%1], 16;" :: "r"(dst), "l"(src) : "memory")
#define CPCOMMIT() asm volatile("cp.async.commit_group;" ::: "memory")
template<int N> __device__ __forceinline__ void cpwait() {
    asm volatile("cp.async.wait_group %0;" :: "n"(N) : "memory");
}
__device__ __forceinline__ uint32_t s2u(const void* p) {
    uint32_t a;
    asm("{ .reg .u64 t; cvta.to.shared.u64 t, %1; cvt.u32.u64 %0, t; }" : "=r"(a) : "l"(p));
    return a;
}

// ---------------------------------------------------------------------------
// k_u: u[b][h] = sum_k W_t[h][k] * o[b, S-1, k]   (exact fp32)
// ---------------------------------------------------------------------------
__global__ void k_u(const float* __restrict__ o, const float* __restrict__ Wt) {
    int b = blockIdx.x, h = threadIdx.x;
    __shared__ float olast[HH];
    olast[h] = o[((size_t)b * SS + (SS - 1)) * HH + h];
    __syncthreads();
    float acc = 0.f;
    const float* wrow = Wt + h * HH;
#pragma unroll 8
    for (int k = 0; k < HH; k++) acc = fmaf(wrow[k], olast[k], acc);
    g_u[b * HH + h] = acc;
}

// ---------------------------------------------------------------------------
// k_prep: W_F -> fp16 m16n8k16 B-fragment image (identical to round 4).
// ---------------------------------------------------------------------------
__global__ void k_prep(const float* __restrict__ WF) {
    int t = blockIdx.x;                 // kstep 0..15
    int tid = threadIdx.x;              // 512
    int p = tid >> 5, l = tid & 31;
    int rq = l >> 2, cq = l & 3;
    int k0 = t * 16 + 2 * cq;
    int na = p * 16 + rq, nb = na + 8;
    uint4 q;
    q.x = packh2(WF[k0 * HH + na],       WF[(k0 + 1) * HH + na]);
    q.y = packh2(WF[(k0 + 8) * HH + na], WF[(k0 + 9) * HH + na]);
    q.z = packh2(WF[k0 * HH + nb],       WF[(k0 + 1) * HH + nb]);
    q.w = packh2(WF[(k0 + 8) * HH + nb], WF[(k0 + 9) * HH + nb]);
    g_Bh[(t * 16 + p) * 32 + l] = q;
}

// ---------------------------------------------------------------------------
// k_main: fused feature+time GEMM (fp16 mma, ldmatrix) + tanh·v_F +
//         split-softmax partials + exact fp32 weighted sums (LDG re-read).
// grid=2048, block=256.
// ---------------------------------------------------------------------------
__global__ void __launch_bounds__(256, 1)
k_main(const float* __restrict__ o, const float* __restrict__ vF) {
    extern __shared__ __align__(16) char smem[];
    const uint32_t sb = s2u(smem);
    const int tid = threadIdx.x, lane = tid & 31, wid = tid >> 5;
    const int tile = blockIdx.x;
    const int b = tile >> 5, s0 = (tile & 31) << 7;
    const int mw = wid & 1;   // M half (64 rows)
    const int nw = wid >> 1;  // N quarter (64 cols)
    const int rq = lane >> 2, cq = lane & 3;

    float* vsh  = (float*)(smem + VSH_OFF);
    float* scT  = (float*)(smem + SCT_OFF);
    float* scF  = (float*)(smem + SCF_OFF);
    float* scTp = (float*)(smem + SCTP_OFF);
    float* scFr = (float*)(smem + SCFR_OFF);
    float* red  = (float*)(smem + RED_OFF);
    uint32_t* uh = (uint32_t*)(smem + UH_OFF);

    const float* obase = o + ((size_t)(b * SS + s0)) * HH;

    // ---- B chunk issue via cp.async (fragment image, 16 KB/chunk) ----
    auto issueB = [&](int c) {
        uint32_t bdst = sb + B_OFF + (c % 3) * 16384;
        const uint4* bsrc = g_Bh + c * 1024;
#pragma unroll
        for (int j = 0; j < 4; j++) {
            int idx = tid + j * 256;
            CP16(bdst + idx * 16, (const void*)(bsrc + idx));
        }
        CPCOMMIT();
    };

    // ---- A prefetch (LDG->regs) and fp16 STS ----
    // thread: row = tid>>1, half = tid&1 (16 cols), 4 float4 per chunk.
    const int arow = tid >> 1, ahalf = tid & 1;
    const float4* aldg = (const float4*)obase + (size_t)arow * 64 + ahalf * 4;
    const uint32_t axor = (uint32_t)(((arow >> 1) & 3) << 4);
    const uint32_t asts = sb + AH_OFF + (uint32_t)arow * 64;

    float4 pf[2][4];
    auto ldgA = [&](int c, int slot) {
#pragma unroll
        for (int k = 0; k < 4; k++) pf[slot][k] = __ldg(aldg + c * 8 + k);
    };
    auto stsA = [&](int c, int slot) {
#pragma unroll
        for (int j = 0; j < 2; j++) {
            uint4 q;
            q.x = packh2(pf[slot][2 * j].x,     pf[slot][2 * j].y);
            q.y = packh2(pf[slot][2 * j].z,     pf[slot][2 * j].w);
            q.z = packh2(pf[slot][2 * j + 1].x, pf[slot][2 * j + 1].y);
            q.w = packh2(pf[slot][2 * j + 1].z, pf[slot][2 * j + 1].w);
            uint32_t s = (uint32_t)(ahalf * 2 + j);
            *(uint4*)(smem + (asts - sb) + c * 8192 + ((s * 16) ^ axor)) = q;
        }
    };

    // ---- prologue ----
    issueB(0); issueB(1);
    ldgA(0, 0); ldgA(1, 1);
    stsA(0, 0);
    vsh[tid] = __ldg(&vF[tid]);
    if (tid < 128)
        uh[tid] = packh2(__ldg(&g_u[b * HH + 2 * tid]), __ldg(&g_u[b * HH + 2 * tid + 1]));

    // ---- ldmatrix lane addressing (per mi) ----
    // row = mw*64 + mi*16 + (lane&7) + ((lane>>3)&1)*8 ; slot16 = (lane>>4)*16
    uint32_t arow_l = (uint32_t)(mw * 64 + (lane & 7) + ((lane >> 3) & 1) * 8);
    uint32_t slot16 = (uint32_t)((lane >> 4) << 4);
    uint32_t lrow[4], lxor[4];
#pragma unroll
    for (int mi = 0; mi < 4; mi++) {
        uint32_t r = arow_l + mi * 16;
        lrow[mi] = sb + AH_OFF + r * 64;
        lxor[mi] = ((r >> 1) & 3) << 4;
    }

    float acc[4][8][4];
#pragma unroll
    for (int mi = 0; mi < 4; mi++)
#pragma unroll
        for (int ni = 0; ni < 8; ni++)
#pragma unroll
            for (int j = 0; j < 4; j++) acc[mi][ni][j] = 0.f;
    float accT[4][4];
#pragma unroll
    for (int mi = 0; mi < 4; mi++)
#pragma unroll
        for (int j = 0; j < 4; j++) accT[mi][j] = 0.f;

    // ---- mainloop over 8 K-chunks of 32 ----
#pragma unroll
    for (int c = 0; c < 8; c++) {
        if (c + 2 < 8) ldgA(c + 2, c & 1);
        if (c + 1 < 8) stsA(c + 1, (c + 1) & 1);
        if (c < 7) cpwait<1>(); else cpwait<0>();
        __syncthreads();
        if (c + 2 < 8) issueB(c + 2);

        const uint4* Bsl = (const uint4*)(smem + B_OFF + (c % 3) * 16384);
        const bool dou = ((c >> 1) == nw);
#pragma unroll
        for (int t = 0; t < 2; t++) {
            uint32_t a[4][4];
#pragma unroll
            for (int mi = 0; mi < 4; mi++)
                ldsm4(a[mi], lrow[mi] + c * 8192 + (((uint32_t)(32 * t) + slot16) ^ lxor[mi]));
            const uint4* bp = Bsl + (t * 16 + nw * 4) * 32 + lane;
#pragma unroll
            for (int p = 0; p < 4; p++) {
                uint4 bq = bp[p * 32];
#pragma unroll
                for (int mi = 0; mi < 4; mi++) {
                    mma16(acc[mi][2 * p],     a[mi][0], a[mi][1], a[mi][2], a[mi][3], bq.x, bq.y);
                    mma16(acc[mi][2 * p + 1], a[mi][0], a[mi][1], a[mi][2], a[mi][3], bq.z, bq.w);
                }
            }
            if (dou) {
                uint32_t bu0 = uh[c * 16 + t * 8 + cq];
                uint32_t bu1 = uh[c * 16 + t * 8 + 4 + cq];
#pragma unroll
                for (int mi = 0; mi < 4; mi++)
                    mma16(accT[mi], a[mi][0], a[mi][1], a[mi][2], a[mi][3], bu0, bu1);
            }
        }
    }

    // ---- feature scores: sf[r] = sum_n tanh(z[r,n]) * v[n] ----
#pragma unroll
    for (int mi = 0; mi < 4; mi++) {
        float s0a = 0.f, s1a = 0.f;
#pragma unroll
        for (int ni = 0; ni < 8; ni++) {
            int n = nw * 64 + ni * 8 + cq * 2;
            float v0 = vsh[n], v1 = vsh[n + 1];
            s0a = fmaf(tanha(acc[mi][ni][0]), v0, s0a);
            s0a = fmaf(tanha(acc[mi][ni][1]), v1, s0a);
            s1a = fmaf(tanha(acc[mi][ni][2]), v0, s1a);
            s1a = fmaf(tanha(acc[mi][ni][3]), v1, s1a);
        }
        s0a += __shfl_xor_sync(0xFFFFFFFFu, s0a, 1);
        s0a += __shfl_xor_sync(0xFFFFFFFFu, s0a, 2);
        s1a += __shfl_xor_sync(0xFFFFFFFFu, s1a, 1);
        s1a += __shfl_xor_sync(0xFFFFFFFFu, s1a, 2);
        if (cq == 0) {
            int r = mw * 64 + mi * 16 + rq;
            scFr[nw * 128 + r] = s0a;
            scFr[nw * 128 + r + 8] = s1a;
            // time-score partials (this warp covered chunks 2nw..2nw+1)
            scTp[nw * 128 + r] = accT[mi][0];
            scTp[nw * 128 + r + 8] = accT[mi][2];
        }
    }
    __syncthreads();
    if (tid < 128)
        scT[tid] = scTp[tid] + scTp[128 + tid] + scTp[256 + tid] + scTp[384 + tid];
    else {
        int i = tid - 128;
        scF[i] = scFr[i] + scFr[128 + i] + scFr[256 + i] + scFr[384 + i];
    }
    __syncthreads();

    // ---- split-softmax partials for both arrays ----
    float* arr = (tid < 128) ? scT : scF;
    int i = tid & 127;
    float v = arr[i];
    float m = v;
#pragma unroll
    for (int off = 16; off; off >>= 1)
        m = fmaxf(m, __shfl_xor_sync(0xFFFFFFFFu, m, off));
    if (lane == 0) red[wid] = m;
    __syncthreads();
    float M = (tid < 128)
        ? fmaxf(fmaxf(red[0], red[1]), fmaxf(red[2], red[3]))
        : fmaxf(fmaxf(red[4], red[5]), fmaxf(red[6], red[7]));
    float e = __expf(v - M);
    float s = e;
#pragma unroll
    for (int off = 16; off; off >>= 1)
        s += __shfl_xor_sync(0xFFFFFFFFu, s, off);
    __syncthreads();
    arr[i] = e;
    if (lane == 0) red[wid] = s;
    __syncthreads();
    if (tid == 0)   { g_mT[tile] = M; g_sT[tile] = red[0] + red[1] + red[2] + red[3]; }
    if (tid == 128) { g_mF[tile] = M; g_sF[tile] = red[4] + red[5] + red[6] + red[7]; }

    // ---- exact fp32 weighted sums: re-read o from L2 via LDG.128 ----
    // thread: g = tid>>6 owns rows g*32..+31, hc = tid&63 owns cols 4hc..+3
    {
        int g = tid >> 6, hc = tid & 63;
        const float4* orow = (const float4*)obase + (size_t)(g * 32) * 64 + hc;
        float4 aT = {0.f, 0.f, 0.f, 0.f}, aF = {0.f, 0.f, 0.f, 0.f};
#pragma unroll 8
        for (int r = 0; r < 32; r++) {
            float4 ov = __ldg(orow + (size_t)r * 64);
            float wT = scT[g * 32 + r], wF = scF[g * 32 + r];
            aT.x = fmaf(wT, ov.x, aT.x); aT.y = fmaf(wT, ov.y, aT.y);
            aT.z = fmaf(wT, ov.z, aT.z); aT.w = fmaf(wT, ov.w, aT.w);
            aF.x = fmaf(wF, ov.x, aF.x); aF.y = fmaf(wF, ov.y, aF.y);
            aF.z = fmaf(wF, ov.z, aF.z); aF.w = fmaf(wF, ov.w, aF.w);
        }
        float* pTs = (float*)(smem + PTS_OFF);
        float* pFs = (float*)(smem + PFS_OFF);
        ((float4*)(pTs + g * 256))[hc] = aT;
        ((float4*)(pFs + g * 256))[hc] = aF;
    }
    __syncthreads();
    {
        float* pTs = (float*)(smem + PTS_OFF);
        float* pFs = (float*)(smem + PFS_OFF);
        g_pT[tile * HH + tid] = pTs[tid] + pTs[256 + tid] + pTs[512 + tid] + pTs[768 + tid];
        g_pF[tile * HH + tid] = pFs[tid] + pFs[256 + tid] + pFs[512 + tid] + pFs[768 + tid];
    }
}

// ---------------------------------------------------------------------------
// k_combine: exact split-softmax merge across the 32 s-tiles of each batch
// ---------------------------------------------------------------------------
__global__ void k_combine(float* __restrict__ out) {
    int b = blockIdx.x, h = threadIdx.x;
    float MT = -1e30f, MF = -1e30f;
#pragma unroll
    for (int c = 0; c < 32; c++) {
        MT = fmaxf(MT, g_mT[b * 32 + c]);
        MF = fmaxf(MF, g_mF[b * 32 + c]);
    }
    float ST = 0.f, SF = 0.f, oT = 0.f, oF = 0.f;
#pragma unroll
    for (int c = 0; c < 32; c++) {
        int t = b * 32 + c;
        float wT = __expf(g_mT[t] - MT), wF = __expf(g_mF[t] - MF);
        ST = fmaf(wT, g_sT[t], ST);
        SF = fmaf(wF, g_sF[t], SF);
        oT = fmaf(wT, g_pT[t * HH + h], oT);
        oF = fmaf(wF, g_pF[t * HH + h], oF);
    }
    out[b * 2 * HH + h] = oT / ST;
    out[b * 2 * HH + HH + h] = oF / SF;
}

// ---------------------------------------------------------------------------
extern "C" void kernel_launch(void* const* d_in, const int* in_sizes, int n_in,
                              void* d_out, int out_size) {
    const float* o  = (const float*)d_in[0];
    const float* Wt = (const float*)d_in[1];
    const float* WF = (const float*)d_in[2];
    const float* vF = (const float*)d_in[3];
    float* out = (float*)d_out;

    cudaFuncSetAttribute(k_main, cudaFuncAttributeMaxDynamicSharedMemorySize, SMEM_TOTAL);

    k_u<<<BB, HH>>>(o, Wt);
    k_prep<<<16, 512>>>(WF);
    k_main<<<NTILES, 256, SMEM_TOTAL>>>(o, vF);
    k_combine<<<BB, HH>>>(out);
}

// round 6
// speedup vs baseline: 10.8036x; 1.1095x over previous
#include <cuda_runtime.h>
#include <cuda_fp16.h>
#include <math.h>
#include <stdint.h>

#define BB 64
#define SS 4096
#define HH 256
#define TM 128
#define NTILES 2048            // BB*SS/TM

// ---------------- device-global scratch (no allocation allowed) -------------
__device__ float g_u[BB * HH];            // W_t @ o_last per batch (fp32)
__device__ uint4 g_Bh[16 * 16 * 32];      // W_F fp16 m16n8k16 B-fragment image (128 KB)
__device__ float g_pT[NTILES * HH];
__device__ float g_pF[NTILES * HH];
__device__ float g_mT[NTILES], g_sT[NTILES], g_mF[NTILES], g_sF[NTILES];

// ---------------- SMEM map (bytes) ------------------------------------------
#define AH_OFF    0            // 2 slots x (128 rows x 64B fp16) = 16384
#define B_OFF     16384        // 3 slots x 16384 = 49152 (fp16 fragments)
#define USH_OFF   65536        // 256 floats (u, fp32)
#define VSH_OFF   66560        // 256 floats
#define SCT_OFF   67584        // 128 floats
#define SCF_OFF   68096        // 128 floats
#define SCFR_OFF  68608        // 4 x 128 floats = 2048
#define RED_OFF   70656        // 32 floats
#define SMEM_TOTAL 70784
// weighted-sum partials reuse the B region after the mainloop:
#define PTS_OFF   B_OFF                 // 8 x 256 floats = 8192
#define PFS_OFF   (B_OFF + 8192)        // 8 x 256 floats

// ---------------- helpers ----------------------------------------------------
__device__ __forceinline__ uint32_t packh2(float lo, float hi) {
    __half2 h = __floats2half2_rn(lo, hi);
    return *(uint32_t*)&h;
}
__device__ __forceinline__ float tanha(float x) {
    float y;
    asm("tanh.approx.f32 %0, %1;" : "=f"(y) : "f"(x));
    return y;
}
__device__ __forceinline__ void mma16(float* c, uint32_t a0, uint32_t a1,
                                      uint32_t a2, uint32_t a3,
                                      uint32_t b0, uint32_t b1) {
    asm volatile(
        "mma.sync.aligned.m16n8k16.row.col.f32.f16.f16.f32 "
        "{%0,%1,%2,%3}, {%4,%5,%6,%7}, {%8,%9}, {%0,%1,%2,%3};"
        : "+f"(c[0]), "+f"(c[1]), "+f"(c[2]), "+f"(c[3])
        : "r"(a0), "r"(a1), "r"(a2), "r"(a3), "r"(b0), "r"(b1));
}
__device__ __forceinline__ void ldsm4(uint32_t* a, uint32_t addr) {
    asm volatile("ldmatrix.sync.aligned.m8n8.x4.shared.b16 {%0,%1,%2,%3}, [%4];"
                 : "=r"(a[0]), "=r"(a[1]), "=r"(a[2]), "=r"(a[3]) : "r"(addr));
}
#define CP16(dst, src) \
    asm volatile("cp.async.cg.shared.global [%0], [%1], 16;" :: "r"(dst), "l"(src) : "memory")
#define CPCOMMIT() asm volatile("cp.async.commit_group;" ::: "memory")
template<int N> __device__ __forceinline__ void cpwait() {
    asm volatile("cp.async.wait_group %0;" :: "n"(N) : "memory");
}
__device__ __forceinline__ uint32_t s2u(const void* p) {
    uint32_t a;
    asm("{ .reg .u64 t; cvta.to.shared.u64 t, %1; cvt.u32.u64 %0, t; }" : "=r"(a) : "l"(p));
    return a;
}

// ---------------------------------------------------------------------------
// k_u: u[b][h] = sum_k W_t[h][k] * o[b, S-1, k]   (exact fp32)
// ---------------------------------------------------------------------------
__global__ void k_u(const float* __restrict__ o, const float* __restrict__ Wt) {
    int b = blockIdx.x, h = threadIdx.x;
    __shared__ float olast[HH];
    olast[h] = o[((size_t)b * SS + (SS - 1)) * HH + h];
    __syncthreads();
    float acc = 0.f;
    const float* wrow = Wt + h * HH;
#pragma unroll 8
    for (int k = 0; k < HH; k++) acc = fmaf(wrow[k], olast[k], acc);
    g_u[b * HH + h] = acc;
}

// ---------------------------------------------------------------------------
// k_prep: W_F -> fp16 m16n8k16 B-fragment image.
// ---------------------------------------------------------------------------
__global__ void k_prep(const float* __restrict__ WF) {
    int t = blockIdx.x;                 // kstep 0..15
    int tid = threadIdx.x;              // 512
    int p = tid >> 5, l = tid & 31;
    int rq = l >> 2, cq = l & 3;
    int k0 = t * 16 + 2 * cq;
    int na = p * 16 + rq, nb = na + 8;
    uint4 q;
    q.x = packh2(WF[k0 * HH + na],       WF[(k0 + 1) * HH + na]);
    q.y = packh2(WF[(k0 + 8) * HH + na], WF[(k0 + 9) * HH + na]);
    q.z = packh2(WF[k0 * HH + nb],       WF[(k0 + 1) * HH + nb]);
    q.w = packh2(WF[(k0 + 8) * HH + nb], WF[(k0 + 9) * HH + nb]);
    g_Bh[(t * 16 + p) * 32 + l] = q;
}

// ---------------------------------------------------------------------------
// k_main: fused feature GEMM (fp16 mma, ldmatrix) + exact fp32 time scores
//         (folded into A prefetch) + tanh·v_F + split-softmax partials +
//         exact fp32 weighted sums (LDG re-read). grid=2048, block=512.
// ---------------------------------------------------------------------------
__global__ void __launch_bounds__(512, 1)
k_main(const float* __restrict__ o, const float* __restrict__ vF) {
    extern __shared__ __align__(16) char smem[];
    const uint32_t sb = s2u(smem);
    const int tid = threadIdx.x, lane = tid & 31, wid = tid >> 5;
    const int tile = blockIdx.x;
    const int b = tile >> 5, s0 = (tile & 31) << 7;
    const int mw = wid & 3;   // M quarter (32 rows)
    const int nw = wid >> 2;  // N quarter (64 cols)
    const int rq = lane >> 2, cq = lane & 3;

    float* ush  = (float*)(smem + USH_OFF);
    float* vsh  = (float*)(smem + VSH_OFF);
    float* scT  = (float*)(smem + SCT_OFF);
    float* scF  = (float*)(smem + SCF_OFF);
    float* scFr = (float*)(smem + SCFR_OFF);
    float* red  = (float*)(smem + RED_OFF);

    const float* obase = o + ((size_t)(b * SS + s0)) * HH;

    // ---- B chunk issue via cp.async (fragment image, 16 KB/chunk) ----
    auto issueB = [&](int c) {
        uint32_t bdst = sb + B_OFF + (c % 3) * 16384;
        const uint4* bsrc = g_Bh + c * 1024;
#pragma unroll
        for (int j = 0; j < 2; j++) {
            int idx = tid + j * 512;
            CP16(bdst + idx * 16, (const void*)(bsrc + idx));
        }
        CPCOMMIT();
    };

    // ---- A prefetch (LDG->fp32 regs), fold time-score FMAs, fp16 STS ----
    // thread: row = tid>>2 (0..127), q = tid&3 (8 cols within the 32-col chunk)
    const int arow = tid >> 2, q = tid & 3;
    const float4* aldg = (const float4*)obase + (size_t)arow * 64 + q * 2;
    const uint32_t axor = (uint32_t)(((arow >> 1) & 3) << 4);
    const uint32_t asts_off = AH_OFF + (uint32_t)arow * 64 + (((uint32_t)q * 16) ^ axor);

    float4 pf[2][2];
    float sT = 0.f;
    auto ldgA = [&](int c, int slot) {
        pf[slot][0] = __ldg(aldg + c * 8);
        pf[slot][1] = __ldg(aldg + c * 8 + 1);
    };
    auto stsA = [&](int c, int slot) {
        const float4 u0 = *(const float4*)(ush + c * 32 + q * 8);
        const float4 u1 = *(const float4*)(ush + c * 32 + q * 8 + 4);
        float4 a0 = pf[slot][0], a1 = pf[slot][1];
        sT = fmaf(a0.x, u0.x, sT); sT = fmaf(a0.y, u0.y, sT);
        sT = fmaf(a0.z, u0.z, sT); sT = fmaf(a0.w, u0.w, sT);
        sT = fmaf(a1.x, u1.x, sT); sT = fmaf(a1.y, u1.y, sT);
        sT = fmaf(a1.z, u1.z, sT); sT = fmaf(a1.w, u1.w, sT);
        uint4 qq;
        qq.x = packh2(a0.x, a0.y); qq.y = packh2(a0.z, a0.w);
        qq.z = packh2(a1.x, a1.y); qq.w = packh2(a1.z, a1.w);
        *(uint4*)(smem + (c & 1) * 8192 + asts_off) = qq;
    };

    // ---- prologue ----
    issueB(0); issueB(1);
    if (tid < 256) {
        ush[tid] = __ldg(&g_u[b * HH + tid]);
        vsh[tid] = __ldg(&vF[tid]);
    }
    ldgA(0, 0); ldgA(1, 1);
    __syncthreads();          // ush visible before stsA(0)
    stsA(0, 0);

    // ---- ldmatrix lane addressing (per mi) ----
    uint32_t arow_l = (uint32_t)(mw * 32 + (lane & 7) + ((lane >> 3) & 1) * 8);
    uint32_t slot16 = (uint32_t)((lane >> 4) << 4);
    uint32_t lrow[2], lxor[2];
#pragma unroll
    for (int mi = 0; mi < 2; mi++) {
        uint32_t r = arow_l + mi * 16;
        lrow[mi] = sb + AH_OFF + r * 64;
        lxor[mi] = ((r >> 1) & 3) << 4;
    }

    float acc[2][8][4];
#pragma unroll
    for (int mi = 0; mi < 2; mi++)
#pragma unroll
        for (int ni = 0; ni < 8; ni++)
#pragma unroll
            for (int j = 0; j < 4; j++) acc[mi][ni][j] = 0.f;

    // ---- mainloop over 8 K-chunks of 32 ----
#pragma unroll
    for (int c = 0; c < 8; c++) {
        if (c < 7) cpwait<1>(); else cpwait<0>();
        __syncthreads();
        if (c + 2 < 8) { issueB(c + 2); ldgA(c + 2, c & 1); }
        if (c + 1 < 8) stsA(c + 1, (c + 1) & 1);

        const uint4* Bsl = (const uint4*)(smem + B_OFF + (c % 3) * 16384);
        const uint32_t aoff = (uint32_t)((c & 1) * 8192);
#pragma unroll
        for (int t = 0; t < 2; t++) {
            uint32_t a[2][4];
#pragma unroll
            for (int mi = 0; mi < 2; mi++)
                ldsm4(a[mi], lrow[mi] + aoff + (((uint32_t)(32 * t) + slot16) ^ lxor[mi]));
            const uint4* bp = Bsl + (t * 16 + nw * 4) * 32 + lane;
#pragma unroll
            for (int p = 0; p < 4; p++) {
                uint4 bq = bp[p * 32];
#pragma unroll
                for (int mi = 0; mi < 2; mi++) {
                    mma16(acc[mi][2 * p],     a[mi][0], a[mi][1], a[mi][2], a[mi][3], bq.x, bq.y);
                    mma16(acc[mi][2 * p + 1], a[mi][0], a[mi][1], a[mi][2], a[mi][3], bq.z, bq.w);
                }
            }
        }
    }

    // ---- feature scores: sf[r] = sum_n tanh(z[r,n]) * v[n] ----
#pragma unroll
    for (int mi = 0; mi < 2; mi++) {
        float s0a = 0.f, s1a = 0.f;
#pragma unroll
        for (int ni = 0; ni < 8; ni++) {
            int n = nw * 64 + ni * 8 + cq * 2;
            float v0 = vsh[n], v1 = vsh[n + 1];
            s0a = fmaf(tanha(acc[mi][ni][0]), v0, s0a);
            s0a = fmaf(tanha(acc[mi][ni][1]), v1, s0a);
            s1a = fmaf(tanha(acc[mi][ni][2]), v0, s1a);
            s1a = fmaf(tanha(acc[mi][ni][3]), v1, s1a);
        }
        s0a += __shfl_xor_sync(0xFFFFFFFFu, s0a, 1);
        s0a += __shfl_xor_sync(0xFFFFFFFFu, s0a, 2);
        s1a += __shfl_xor_sync(0xFFFFFFFFu, s1a, 1);
        s1a += __shfl_xor_sync(0xFFFFFFFFu, s1a, 2);
        if (cq == 0) {
            int r = mw * 32 + mi * 16 + rq;
            scFr[nw * 128 + r] = s0a;
            scFr[nw * 128 + r + 8] = s1a;
        }
    }

    // ---- exact fp32 time scores: reduce over the 4 threads sharing a row ----
    sT += __shfl_xor_sync(0xFFFFFFFFu, sT, 1);
    sT += __shfl_xor_sync(0xFFFFFFFFu, sT, 2);
    if ((lane & 3) == 0) scT[arow] = sT;
    __syncthreads();
    if (tid < 128)
        scF[tid] = scFr[tid] + scFr[128 + tid] + scFr[256 + tid] + scFr[384 + tid];
    __syncthreads();

    // ---- split-softmax partials for both arrays (warps 0..7 active) ----
    float vv = 0.f, ee = 0.f;
    float* arr = (tid < 128) ? scT : scF;
    int i = tid & 127;
    if (tid < 256) {
        vv = arr[i];
        float m = vv;
#pragma unroll
        for (int off = 16; off; off >>= 1)
            m = fmaxf(m, __shfl_xor_sync(0xFFFFFFFFu, m, off));
        if (lane == 0) red[wid] = m;
    }
    __syncthreads();
    float M = 0.f;
    if (tid < 256) {
        M = (tid < 128)
            ? fmaxf(fmaxf(red[0], red[1]), fmaxf(red[2], red[3]))
            : fmaxf(fmaxf(red[4], red[5]), fmaxf(red[6], red[7]));
        ee = __expf(vv - M);
        float s = ee;
#pragma unroll
        for (int off = 16; off; off >>= 1)
            s += __shfl_xor_sync(0xFFFFFFFFu, s, off);
        if (lane == 0) red[16 + wid] = s;
    }
    __syncthreads();
    if (tid < 256) arr[i] = ee;
    __syncthreads();
    if (tid == 0)   { g_mT[tile] = M; g_sT[tile] = red[16] + red[17] + red[18] + red[19]; }
    if (tid == 128) { g_mF[tile] = M; g_sF[tile] = red[20] + red[21] + red[22] + red[23]; }

    // ---- exact fp32 weighted sums: re-read o from L2 via LDG.128 ----
    // thread: g = tid>>6 owns rows g*16..+15, hc = tid&63 owns cols 4hc..+3
    {
        int g = tid >> 6, hc = tid & 63;
        const float4* orow = (const float4*)obase + (size_t)(g * 16) * 64 + hc;
        float4 aT = {0.f, 0.f, 0.f, 0.f}, aF = {0.f, 0.f, 0.f, 0.f};
#pragma unroll 8
        for (int r = 0; r < 16; r++) {
            float4 ov = __ldg(orow + (size_t)r * 64);
            float wT = scT[g * 16 + r], wF = scF[g * 16 + r];
            aT.x = fmaf(wT, ov.x, aT.x); aT.y = fmaf(wT, ov.y, aT.y);
            aT.z = fmaf(wT, ov.z, aT.z); aT.w = fmaf(wT, ov.w, aT.w);
            aF.x = fmaf(wF, ov.x, aF.x); aF.y = fmaf(wF, ov.y, aF.y);
            aF.z = fmaf(wF, ov.z, aF.z); aF.w = fmaf(wF, ov.w, aF.w);
        }
        float* pTs = (float*)(smem + PTS_OFF);
        float* pFs = (float*)(smem + PFS_OFF);
        ((float4*)(pTs + g * 256))[hc] = aT;
        ((float4*)(pFs + g * 256))[hc] = aF;
    }
    __syncthreads();
    {
        float* pTs = (float*)(smem + PTS_OFF);
        float* pFs = (float*)(smem + PFS_OFF);
        if (tid < 256) {
            float a = 0.f;
#pragma unroll
            for (int g = 0; g < 8; g++) a += pTs[g * 256 + tid];
            g_pT[tile * HH + tid] = a;
        } else {
            int j = tid - 256;
            float a = 0.f;
#pragma unroll
            for (int g = 0; g < 8; g++) a += pFs[g * 256 + j];
            g_pF[tile * HH + j] = a;
        }
    }
}

// ---------------------------------------------------------------------------
// k_combine: exact split-softmax merge across the 32 s-tiles of each batch
// ---------------------------------------------------------------------------
__global__ void k_combine(float* __restrict__ out) {
    int b = blockIdx.x, h = threadIdx.x;
    float MT = -1e30f, MF = -1e30f;
#pragma unroll
    for (int c = 0; c < 32; c++) {
        MT = fmaxf(MT, g_mT[b * 32 + c]);
        MF = fmaxf(MF, g_mF[b * 32 + c]);
    }
    float ST = 0.f, SF = 0.f, oT = 0.f, oF = 0.f;
#pragma unroll
    for (int c = 0; c < 32; c++) {
        int t = b * 32 + c;
        float wT = __expf(g_mT[t] - MT), wF = __expf(g_mF[t] - MF);
        ST = fmaf(wT, g_sT[t], ST);
        SF = fmaf(wF, g_sF[t], SF);
        oT = fmaf(wT, g_pT[t * HH + h], oT);
        oF = fmaf(wF, g_pF[t * HH + h], oF);
    }
    out[b * 2 * HH + h] = oT / ST;
    out[b * 2 * HH + HH + h] = oF / SF;
}

// ---------------------------------------------------------------------------
extern "C" void kernel_launch(void* const* d_in, const int* in_sizes, int n_in,
                              void* d_out, int out_size) {
    const float* o  = (const float*)d_in[0];
    const float* Wt = (const float*)d_in[1];
    const float* WF = (const float*)d_in[2];
    const float* vF = (const float*)d_in[3];
    float* out = (float*)d_out;

    cudaFuncSetAttribute(k_main, cudaFuncAttributeMaxDynamicSharedMemorySize, SMEM_TOTAL);

    k_u<<<BB, HH>>>(o, Wt);
    k_prep<<<16, 512>>>(WF);
    k_main<<<NTILES, 512, SMEM_TOTAL>>>(o, vF);
    k_combine<<<BB, HH>>>(out);
}